// round 10
// baseline (speedup 1.0000x reference)
#include <cuda_runtime.h>
#include <cuda_fp16.h>
#include <stdint.h>

#define NTHREADS 384
#define TILE_ROWS 384                // 12 warps x 32 rows
#define WST 72                       // padded smem stride (halfs) -> conflict-free ldmatrix
#define MAT_HALFS (64 * WST)         // 4608 halfs per 64x64 matrix
#define NMAT 11
#define W_HALFS (NMAT * MAT_HALFS)
#define F32_FLOATS 512
#define PB_WORDS 160
#define SMEM_BYTES (W_HALFS * 2 + F32_FLOATS * 4 + PB_WORDS * 4)

// f32 scalar region offsets (floats)
#define F_M1W 0
#define F_M1B 192
#define F_SW  256
#define F_SB  384
#define F_EW  448
// packed f16x2 bias region offsets (uint32 words)
#define PB_M2 0
#define PB_M3 32
#define PB_A0 64     // +32 per alpha head

// matrix slots in smem
#define M_M2 0
#define M_M3 1
#define M_A0 2
#define M_A1 3
#define M_A2 4
#define M_C0 5
#define M_R0 8

struct Params {
    const float *x, *t, *beta, *nu, *rho;
    const float *start_w, *start_b, *end_w, *end_b;
    const float *m1_w, *m1_b, *m2_w, *m2_b, *m3_w, *m3_b;
    const float *a0_w, *a0_b, *a1_w, *a1_b, *a2_w, *a2_b;
    const float *col0, *col1, *col2, *row0, *row1, *row2;
    float* out;
    int ntiles;
    int B;
};

__device__ __forceinline__ uint32_t pack2(float lo, float hi) {
    __half2 h = __floats2half2_rn(lo, hi);
    return *reinterpret_cast<uint32_t*>(&h);
}
__device__ __forceinline__ float2 unpack2(uint32_t v) {
    __half2 h = *reinterpret_cast<__half2*>(&v);
    return __half22float2(h);
}
__device__ __forceinline__ uint32_t htanh2(uint32_t v) {
    uint32_t y;
    asm("tanh.approx.f16x2 %0, %1;" : "=r"(y) : "r"(v));
    return y;
}
__device__ __forceinline__ uint32_t hadd2u(uint32_t a, uint32_t b) {
    __half2 r = __hadd2(*reinterpret_cast<__half2*>(&a), *reinterpret_cast<__half2*>(&b));
    return *reinterpret_cast<uint32_t*>(&r);
}
__device__ __forceinline__ uint32_t hmul2u(uint32_t a, uint32_t b) {
    __half2 r = __hmul2(*reinterpret_cast<__half2*>(&a), *reinterpret_cast<__half2*>(&b));
    return *reinterpret_cast<uint32_t*>(&r);
}
__device__ __forceinline__ uint32_t hrelu2(uint32_t a) {
    __half2 z = __float2half2_rn(0.f);
    __half2 r = __hmax2(*reinterpret_cast<__half2*>(&a), z);
    return *reinterpret_cast<uint32_t*>(&r);
}

__device__ __forceinline__ void mma16816h(uint32_t* c, const uint32_t* a, uint32_t b0, uint32_t b1) {
    asm volatile(
        "mma.sync.aligned.m16n8k16.row.col.f16.f16.f16.f16 "
        "{%0,%1}, {%2,%3,%4,%5}, {%6,%7}, {%0,%1};\n"
        : "+r"(c[0]), "+r"(c[1])
        : "r"(a[0]), "r"(a[1]), "r"(a[2]), "r"(a[3]), "r"(b0), "r"(b1));
}

__device__ __forceinline__ void ldsm4t(uint32_t& r0, uint32_t& r1, uint32_t& r2, uint32_t& r3,
                                       uint32_t addr) {
    asm volatile("ldmatrix.sync.aligned.m8n8.x4.trans.shared.b16 {%0,%1,%2,%3}, [%4];\n"
                 : "=r"(r0), "=r"(r1), "=r"(r2), "=r"(r3)
                 : "r"(addr));
}

// Dual-tile f16-accum GEMM: C[h][8][2] = A[h](16x64) @ W(64x64), h=0,1.
__device__ __forceinline__ void gemm64x2h(uint32_t C[2][8][2], const uint32_t A[2][4][4],
                                          const __half* W, int lane) {
#pragma unroll
    for (int h = 0; h < 2; h++)
#pragma unroll
        for (int nt = 0; nt < 8; nt++) { C[h][nt][0] = 0u; C[h][nt][1] = 0u; }

    uint32_t base = (uint32_t)__cvta_generic_to_shared(
        W + (lane & 15) * WST + ((lane & 16) ? 8 : 0));
#pragma unroll
    for (int nt2 = 0; nt2 < 4; nt2++) {
#pragma unroll
        for (int kb = 0; kb < 4; kb++) {
            uint32_t b0, b1, b2, b3;
            ldsm4t(b0, b1, b2, b3, base + (uint32_t)((kb * 16 * WST + nt2 * 16) * 2));
            mma16816h(C[0][nt2 * 2],     A[0][kb], b0, b1);
            mma16816h(C[0][nt2 * 2 + 1], A[0][kb], b2, b3);
            mma16816h(C[1][nt2 * 2],     A[1][kb], b0, b1);
            mma16816h(C[1][nt2 * 2 + 1], A[1][kb], b2, b3);
        }
    }
}

// Fused pair of independent dual-tile GEMMs (different A and W each):
// Ca = Aa @ Wa  and  Cc = Ac @ Wc, interleaved for 2x MMA ILP, no boundary.
__device__ __forceinline__ void gemm64x2h_dual(
    uint32_t Ca[2][8][2], const uint32_t Aa[2][4][4], const __half* Wa,
    uint32_t Cc[2][8][2], const uint32_t Ac[2][4][4], const __half* Wc, int lane) {
#pragma unroll
    for (int h = 0; h < 2; h++)
#pragma unroll
        for (int nt = 0; nt < 8; nt++) {
            Ca[h][nt][0] = 0u; Ca[h][nt][1] = 0u;
            Cc[h][nt][0] = 0u; Cc[h][nt][1] = 0u;
        }

    uint32_t off = (lane & 15) * WST + ((lane & 16) ? 8 : 0);
    uint32_t basea = (uint32_t)__cvta_generic_to_shared(Wa + off);
    uint32_t basec = (uint32_t)__cvta_generic_to_shared(Wc + off);
#pragma unroll
    for (int nt2 = 0; nt2 < 4; nt2++) {
#pragma unroll
        for (int kb = 0; kb < 4; kb++) {
            uint32_t d = (uint32_t)((kb * 16 * WST + nt2 * 16) * 2);
            uint32_t a0, a1, a2, a3, c0, c1, c2, c3;
            ldsm4t(a0, a1, a2, a3, basea + d);
            ldsm4t(c0, c1, c2, c3, basec + d);
            mma16816h(Ca[0][nt2 * 2],     Aa[0][kb], a0, a1);
            mma16816h(Cc[0][nt2 * 2],     Ac[0][kb], c0, c1);
            mma16816h(Ca[0][nt2 * 2 + 1], Aa[0][kb], a2, a3);
            mma16816h(Cc[0][nt2 * 2 + 1], Ac[0][kb], c2, c3);
            mma16816h(Ca[1][nt2 * 2],     Aa[1][kb], a0, a1);
            mma16816h(Cc[1][nt2 * 2],     Ac[1][kb], c0, c1);
            mma16816h(Ca[1][nt2 * 2 + 1], Aa[1][kb], a2, a3);
            mma16816h(Cc[1][nt2 * 2 + 1], Ac[1][kb], c2, c3);
        }
    }
}

__device__ __forceinline__ void add_bias2h(uint32_t C[2][8][2], const uint32_t* pb, int tig) {
#pragma unroll
    for (int h = 0; h < 2; h++)
#pragma unroll
        for (int nt = 0; nt < 8; nt++) {
            uint32_t b = pb[nt * 4 + tig];
            C[h][nt][0] = hadd2u(C[h][nt][0], b);
            C[h][nt][1] = hadd2u(C[h][nt][1], b);
        }
}

// f16 C layout == A-fragment layout: repack is a register rename (+ tanh)
__device__ __forceinline__ void repack_tanh2h(const uint32_t C[2][8][2], uint32_t A[2][4][4]) {
#pragma unroll
    for (int h = 0; h < 2; h++)
#pragma unroll
        for (int kb = 0; kb < 4; kb++) {
            A[h][kb][0] = htanh2(C[h][2 * kb][0]);
            A[h][kb][1] = htanh2(C[h][2 * kb][1]);
            A[h][kb][2] = htanh2(C[h][2 * kb + 1][0]);
            A[h][kb][3] = htanh2(C[h][2 * kb + 1][1]);
        }
}
__device__ __forceinline__ void repack_id2h(const uint32_t C[2][8][2], uint32_t A[2][4][4]) {
#pragma unroll
    for (int h = 0; h < 2; h++)
#pragma unroll
        for (int kb = 0; kb < 4; kb++) {
            A[h][kb][0] = C[h][2 * kb][0];
            A[h][kb][1] = C[h][2 * kb][1];
            A[h][kb][2] = C[h][2 * kb + 1][0];
            A[h][kb][3] = C[h][2 * kb + 1][1];
        }
}

__global__ void __launch_bounds__(NTHREADS, 1)
pinn_kernel(Params p) {
    extern __shared__ char smem_raw[];
    __half* smW = reinterpret_cast<__half*>(smem_raw);
    float* smF = reinterpret_cast<float*>(smem_raw + W_HALFS * 2);
    uint32_t* smPB = reinterpret_cast<uint32_t*>(smem_raw + W_HALFS * 2 + F32_FLOATS * 4);
    const int tid = threadIdx.x;

    // ---- fold in the pass-through copy (24576 floats = 6144 float4, 16 blocks x 384) ----
    if (blockIdx.x < 16) {
        int i = blockIdx.x * NTHREADS + tid;
        int j = i & 1023;
        int m = i >> 10;
        const float* srcs[6] = {p.col0, p.col1, p.col2, p.row0, p.row1, p.row2};
        const float4* s4 = reinterpret_cast<const float4*>(srcs[m]) + j;
        reinterpret_cast<float4*>(p.out + p.B)[i] = *s4;
    }

    // ---- stage weights (fp32 -> fp16, padded stride) + scalars + packed biases ----
    {
        const float* gsrc[NMAT] = {p.m2_w, p.m3_w, p.a0_w, p.a1_w, p.a2_w,
                                   p.col0, p.col1, p.col2, p.row0, p.row1, p.row2};
#pragma unroll
        for (int m = 0; m < NMAT; m++) {
            const float* src = gsrc[m];
            __half* dst = smW + m * MAT_HALFS;
            for (int i = tid; i < 4096; i += NTHREADS)
                dst[(i >> 6) * WST + (i & 63)] = __float2half_rn(src[i]);
        }
        if (tid < 192) smF[F_M1W + tid] = p.m1_w[tid];
        if (tid < 128) smF[F_SW + tid] = p.start_w[tid];
        if (tid < 64) {
            smF[F_M1B + tid] = p.m1_b[tid];
            smF[F_SB + tid]  = p.start_b[tid];
            smF[F_EW  + tid] = p.end_w[tid];
        }
        if (tid < 32) {
            int nt = tid >> 2, tg = tid & 3;
            int j0 = nt * 8 + tg * 2;
            smPB[PB_M2 + tid]      = pack2(p.m2_b[j0], p.m2_b[j0 + 1]);
            smPB[PB_M3 + tid]      = pack2(p.m3_b[j0], p.m3_b[j0 + 1]);
            smPB[PB_A0 + tid]      = pack2(p.a0_b[j0], p.a0_b[j0 + 1]);
            smPB[PB_A0 + 32 + tid] = pack2(p.a1_b[j0], p.a1_b[j0 + 1]);
            smPB[PB_A0 + 64 + tid] = pack2(p.a2_b[j0], p.a2_b[j0 + 1]);
        }
    }
    __syncthreads();

    const int lane = tid & 31, warp = tid >> 5;
    const int g = lane >> 2, tig = lane & 3;
    const float eb = p.end_b[0];

    for (int tile = blockIdx.x; tile < p.ntiles; tile += gridDim.x) {
        const int rowbase = tile * TILE_ROWS + warp * 32;   // 32 rows per warp
        if (rowbase >= p.B) continue;   // tail tile: whole warps drop out (no sync in loop)

        uint32_t Mst[2][4][4];  // hypernet state (f16 A-frags)
        uint32_t A[2][4][4];    // main-net h (f16 A-frags)
        uint32_t Ca[2][8][2];   // alpha / generic accumulators
        uint32_t Cc[2][8][2];   // col-chain accumulators

        // ---- hypernet input layer: tanh([beta,nu,rho] @ m1_w + m1_b) ----
#pragma unroll
        for (int h = 0; h < 2; h++) {
            const int rlo = rowbase + h * 16 + g, rhi = rlo + 8;
            float b0 = p.beta[rlo], b1 = p.beta[rhi];
            float n0 = p.nu[rlo],   n1 = p.nu[rhi];
            float r0 = p.rho[rlo],  r1 = p.rho[rhi];
#pragma unroll
            for (int kb = 0; kb < 4; kb++) {
                int j0 = kb * 16 + tig * 2;
#pragma unroll
                for (int hf = 0; hf < 2; hf++) {
                    int j = j0 + hf * 8;
                    float w0a = smF[F_M1W + j],        w0b = smF[F_M1W + j + 1];
                    float w1a = smF[F_M1W + 64 + j],   w1b = smF[F_M1W + 64 + j + 1];
                    float w2a = smF[F_M1W + 128 + j],  w2b = smF[F_M1W + 128 + j + 1];
                    float ba  = smF[F_M1B + j],        bb  = smF[F_M1B + j + 1];
                    Mst[h][kb][hf * 2 + 0] = htanh2(pack2(b0 * w0a + n0 * w1a + r0 * w2a + ba,
                                                          b0 * w0b + n0 * w1b + r0 * w2b + bb));
                    Mst[h][kb][hf * 2 + 1] = htanh2(pack2(b1 * w0a + n1 * w1a + r1 * w2a + ba,
                                                          b1 * w0b + n1 * w1b + r1 * w2b + bb));
                }
            }
        }

        // ---- main net input layer (independent of m2/m3 — gives overlap work) ----
#pragma unroll
        for (int h = 0; h < 2; h++) {
            const int rlo = rowbase + h * 16 + g, rhi = rlo + 8;
            float x0 = p.x[rlo], x1 = p.x[rhi];
            float t0 = p.t[rlo], t1 = p.t[rhi];
#pragma unroll
            for (int kb = 0; kb < 4; kb++) {
                int j0 = kb * 16 + tig * 2;
#pragma unroll
                for (int hf = 0; hf < 2; hf++) {
                    int j = j0 + hf * 8;
                    float w0a = smF[F_SW + j],      w0b = smF[F_SW + j + 1];
                    float w1a = smF[F_SW + 64 + j], w1b = smF[F_SW + 64 + j + 1];
                    float ba  = smF[F_SB + j],      bb  = smF[F_SB + j + 1];
                    A[h][kb][hf * 2 + 0] = htanh2(pack2(x0 * w0a + t0 * w1a + ba,
                                                        x0 * w0b + t0 * w1b + bb));
                    A[h][kb][hf * 2 + 1] = htanh2(pack2(x1 * w0a + t1 * w1a + ba,
                                                        x1 * w0b + t1 * w1b + bb));
                }
            }
        }

        // m2, m3 (tanh)
        gemm64x2h(Ca, Mst, smW + M_M2 * MAT_HALFS, lane);
        add_bias2h(Ca, smPB + PB_M2, tig);
        repack_tanh2h(Ca, Mst);
        gemm64x2h(Ca, Mst, smW + M_M3 * MAT_HALFS, lane);
        add_bias2h(Ca, smPB + PB_M3, tig);
        repack_tanh2h(Ca, Mst);

        // ---- 3x: fused (alpha_l GEMM || col_l GEMM), then mul/relu, then row_l ----
#pragma unroll
        for (int l = 0; l < 3; l++) {
            gemm64x2h_dual(Ca, Mst, smW + (M_A0 + l) * MAT_HALFS,
                           Cc, A,   smW + (M_C0 + l) * MAT_HALFS, lane);
            add_bias2h(Ca, smPB + PB_A0 + 32 * l, tig);
#pragma unroll
            for (int h = 0; h < 2; h++)
#pragma unroll
                for (int nt = 0; nt < 8; nt++) {
                    Cc[h][nt][0] = hmul2u(Cc[h][nt][0], hrelu2(Ca[h][nt][0]));
                    Cc[h][nt][1] = hmul2u(Cc[h][nt][1], hrelu2(Ca[h][nt][1]));
                }
            repack_id2h(Cc, A);
            gemm64x2h(Ca, A, smW + (M_R0 + l) * MAT_HALFS, lane);
            repack_tanh2h(Ca, A);
        }

        // ---- out = h @ end_w + end_b (f32 dot) ----
#pragma unroll
        for (int h = 0; h < 2; h++) {
            const int rlo = rowbase + h * 16 + g, rhi = rlo + 8;
            float slo = 0.f, shi = 0.f;
#pragma unroll
            for (int kb = 0; kb < 4; kb++) {
                int j0 = kb * 16 + tig * 2;
                float2 f;
                f = unpack2(A[h][kb][0]); slo += f.x * smF[F_EW + j0]     + f.y * smF[F_EW + j0 + 1];
                f = unpack2(A[h][kb][1]); shi += f.x * smF[F_EW + j0]     + f.y * smF[F_EW + j0 + 1];
                f = unpack2(A[h][kb][2]); slo += f.x * smF[F_EW + j0 + 8] + f.y * smF[F_EW + j0 + 9];
                f = unpack2(A[h][kb][3]); shi += f.x * smF[F_EW + j0 + 8] + f.y * smF[F_EW + j0 + 9];
            }
            slo += __shfl_xor_sync(0xFFFFFFFFu, slo, 1);
            slo += __shfl_xor_sync(0xFFFFFFFFu, slo, 2);
            shi += __shfl_xor_sync(0xFFFFFFFFu, shi, 1);
            shi += __shfl_xor_sync(0xFFFFFFFFu, shi, 2);
            if (tig == 0) {
                p.out[rlo] = slo + eb;
                p.out[rhi] = shi + eb;
            }
        }
    }
}

extern "C" void kernel_launch(void* const* d_in, const int* in_sizes, int n_in,
                              void* d_out, int out_size) {
    (void)n_in; (void)out_size;
    Params p;
    p.x       = (const float*)d_in[0];
    p.t       = (const float*)d_in[1];
    p.beta    = (const float*)d_in[2];
    p.nu      = (const float*)d_in[3];
    p.rho     = (const float*)d_in[4];
    p.start_w = (const float*)d_in[5];
    p.start_b = (const float*)d_in[6];
    p.end_w   = (const float*)d_in[7];
    p.end_b   = (const float*)d_in[8];
    p.m1_w    = (const float*)d_in[9];
    p.m1_b    = (const float*)d_in[10];
    p.m2_w    = (const float*)d_in[11];
    p.m2_b    = (const float*)d_in[12];
    p.m3_w    = (const float*)d_in[13];
    p.m3_b    = (const float*)d_in[14];
    p.a0_w    = (const float*)d_in[15];
    p.a0_b    = (const float*)d_in[16];
    p.a1_w    = (const float*)d_in[17];
    p.a1_b    = (const float*)d_in[18];
    p.a2_w    = (const float*)d_in[19];
    p.a2_b    = (const float*)d_in[20];
    p.col0    = (const float*)d_in[21];
    p.col1    = (const float*)d_in[22];
    p.col2    = (const float*)d_in[23];
    p.row0    = (const float*)d_in[24];
    p.row1    = (const float*)d_in[25];
    p.row2    = (const float*)d_in[26];
    p.out     = (float*)d_out;

    p.B = in_sizes[0];
    p.ntiles = (p.B + TILE_ROWS - 1) / TILE_ROWS;

    int dev = 0, nsm = 148;
    cudaGetDevice(&dev);
    cudaDeviceGetAttribute(&nsm, cudaDevAttrMultiProcessorCount, dev);
    int grid = nsm < 16 ? 16 : nsm;   // >=16 so the folded copy covers all 6 matrices
    if (grid > p.ntiles) grid = p.ntiles;

    cudaFuncSetAttribute(pinn_kernel, cudaFuncAttributeMaxDynamicSharedMemorySize, SMEM_BYTES);
    pinn_kernel<<<grid, NTHREADS, SMEM_BYTES>>>(p);
}

// round 11
// speedup vs baseline: 1.0407x; 1.0407x over previous
#include <cuda_runtime.h>
#include <cuda_fp16.h>
#include <stdint.h>

#define NTHREADS 384
#define TILE_ROWS 384                // 12 warps x 32 rows
#define WST 72                       // padded smem stride (halfs) -> conflict-free ldmatrix
#define MAT_HALFS (64 * WST)         // 4608 halfs per 64x64 matrix
#define NMAT 11
#define W_HALFS (NMAT * MAT_HALFS)
#define IN_HALFS (16 * WST)          // 16x64 input-layer tile (K=16)
#define F32_FLOATS 64                // end_w
#define PB_WORDS 160
#define SMEM_BYTES ((W_HALFS + 2 * IN_HALFS) * 2 + F32_FLOATS * 4 + PB_WORDS * 4)

#define F_EW 0
// packed f16x2 bias region offsets (uint32 words)
#define PB_M2 0
#define PB_M3 32
#define PB_A0 64     // +32 per alpha head

// matrix slots in smem
#define M_M2 0
#define M_M3 1
#define M_A0 2
#define M_A1 3
#define M_A2 4
#define M_C0 5
#define M_R0 8
// input-layer tiles sit after the 11 square matrices
#define IN_M1 0
#define IN_ST 1

struct Params {
    const float *x, *t, *beta, *nu, *rho;
    const float *start_w, *start_b, *end_w, *end_b;
    const float *m1_w, *m1_b, *m2_w, *m2_b, *m3_w, *m3_b;
    const float *a0_w, *a0_b, *a1_w, *a1_b, *a2_w, *a2_b;
    const float *col0, *col1, *col2, *row0, *row1, *row2;
    float* out;
    int ntiles;
    int B;
};

__device__ __forceinline__ uint32_t pack2(float lo, float hi) {
    __half2 h = __floats2half2_rn(lo, hi);
    return *reinterpret_cast<uint32_t*>(&h);
}
__device__ __forceinline__ float2 unpack2(uint32_t v) {
    __half2 h = *reinterpret_cast<__half2*>(&v);
    return __half22float2(h);
}
__device__ __forceinline__ uint32_t htanh2(uint32_t v) {
    uint32_t y;
    asm("tanh.approx.f16x2 %0, %1;" : "=r"(y) : "r"(v));
    return y;
}
__device__ __forceinline__ uint32_t hadd2u(uint32_t a, uint32_t b) {
    __half2 r = __hadd2(*reinterpret_cast<__half2*>(&a), *reinterpret_cast<__half2*>(&b));
    return *reinterpret_cast<uint32_t*>(&r);
}
__device__ __forceinline__ uint32_t hmul2u(uint32_t a, uint32_t b) {
    __half2 r = __hmul2(*reinterpret_cast<__half2*>(&a), *reinterpret_cast<__half2*>(&b));
    return *reinterpret_cast<uint32_t*>(&r);
}
__device__ __forceinline__ uint32_t hrelu2(uint32_t a) {
    __half2 z = __float2half2_rn(0.f);
    __half2 r = __hmax2(*reinterpret_cast<__half2*>(&a), z);
    return *reinterpret_cast<uint32_t*>(&r);
}

__device__ __forceinline__ void mma16816h(uint32_t* c, const uint32_t* a, uint32_t b0, uint32_t b1) {
    asm volatile(
        "mma.sync.aligned.m16n8k16.row.col.f16.f16.f16.f16 "
        "{%0,%1}, {%2,%3,%4,%5}, {%6,%7}, {%0,%1};\n"
        : "+r"(c[0]), "+r"(c[1])
        : "r"(a[0]), "r"(a[1]), "r"(a[2]), "r"(a[3]), "r"(b0), "r"(b1));
}

__device__ __forceinline__ void ldsm4t(uint32_t& r0, uint32_t& r1, uint32_t& r2, uint32_t& r3,
                                       uint32_t addr) {
    asm volatile("ldmatrix.sync.aligned.m8n8.x4.trans.shared.b16 {%0,%1,%2,%3}, [%4];\n"
                 : "=r"(r0), "=r"(r1), "=r"(r2), "=r"(r3)
                 : "r"(addr));
}

// Dual-tile f16-accum GEMM: C[h][8][2] = A[h](16x64) @ W(64x64), h=0,1.
__device__ __forceinline__ void gemm64x2h(uint32_t C[2][8][2], const uint32_t A[2][4][4],
                                          const __half* W, int lane) {
#pragma unroll
    for (int h = 0; h < 2; h++)
#pragma unroll
        for (int nt = 0; nt < 8; nt++) { C[h][nt][0] = 0u; C[h][nt][1] = 0u; }

    uint32_t base = (uint32_t)__cvta_generic_to_shared(
        W + (lane & 15) * WST + ((lane & 16) ? 8 : 0));
#pragma unroll
    for (int nt2 = 0; nt2 < 4; nt2++) {
#pragma unroll
        for (int kb = 0; kb < 4; kb++) {
            uint32_t b0, b1, b2, b3;
            ldsm4t(b0, b1, b2, b3, base + (uint32_t)((kb * 16 * WST + nt2 * 16) * 2));
            mma16816h(C[0][nt2 * 2],     A[0][kb], b0, b1);
            mma16816h(C[0][nt2 * 2 + 1], A[0][kb], b2, b3);
            mma16816h(C[1][nt2 * 2],     A[1][kb], b0, b1);
            mma16816h(C[1][nt2 * 2 + 1], A[1][kb], b2, b3);
        }
    }
}

// Fused input layers: K=16 GEMMs for m1 ([beta,nu,rho,1]) and start ([x,t,1]),
// dual row-halves each. Biases are folded in as weight rows.
__device__ __forceinline__ void gemm_in(uint32_t Cm[2][8][2], const uint32_t Am[2][4],
                                        uint32_t Ci[2][8][2], const uint32_t Ai[2][4],
                                        const __half* Wm, const __half* Wi, int lane) {
#pragma unroll
    for (int h = 0; h < 2; h++)
#pragma unroll
        for (int nt = 0; nt < 8; nt++) {
            Cm[h][nt][0] = 0u; Cm[h][nt][1] = 0u;
            Ci[h][nt][0] = 0u; Ci[h][nt][1] = 0u;
        }
    uint32_t off = (lane & 15) * WST + ((lane & 16) ? 8 : 0);
    uint32_t basem = (uint32_t)__cvta_generic_to_shared(Wm + off);
    uint32_t basei = (uint32_t)__cvta_generic_to_shared(Wi + off);
#pragma unroll
    for (int nt2 = 0; nt2 < 4; nt2++) {
        uint32_t d = (uint32_t)((nt2 * 16) * 2);
        uint32_t m0, m1, m2, m3, i0, i1, i2, i3;
        ldsm4t(m0, m1, m2, m3, basem + d);
        ldsm4t(i0, i1, i2, i3, basei + d);
        mma16816h(Cm[0][nt2 * 2],     Am[0], m0, m1);
        mma16816h(Cm[0][nt2 * 2 + 1], Am[0], m2, m3);
        mma16816h(Cm[1][nt2 * 2],     Am[1], m0, m1);
        mma16816h(Cm[1][nt2 * 2 + 1], Am[1], m2, m3);
        mma16816h(Ci[0][nt2 * 2],     Ai[0], i0, i1);
        mma16816h(Ci[0][nt2 * 2 + 1], Ai[0], i2, i3);
        mma16816h(Ci[1][nt2 * 2],     Ai[1], i0, i1);
        mma16816h(Ci[1][nt2 * 2 + 1], Ai[1], i2, i3);
    }
}

__device__ __forceinline__ void add_bias2h(uint32_t C[2][8][2], const uint32_t* pb, int tig) {
#pragma unroll
    for (int h = 0; h < 2; h++)
#pragma unroll
        for (int nt = 0; nt < 8; nt++) {
            uint32_t b = pb[nt * 4 + tig];
            C[h][nt][0] = hadd2u(C[h][nt][0], b);
            C[h][nt][1] = hadd2u(C[h][nt][1], b);
        }
}

// f16 C layout == A-fragment layout: repack is a register rename (+ tanh)
__device__ __forceinline__ void repack_tanh2h(const uint32_t C[2][8][2], uint32_t A[2][4][4]) {
#pragma unroll
    for (int h = 0; h < 2; h++)
#pragma unroll
        for (int kb = 0; kb < 4; kb++) {
            A[h][kb][0] = htanh2(C[h][2 * kb][0]);
            A[h][kb][1] = htanh2(C[h][2 * kb][1]);
            A[h][kb][2] = htanh2(C[h][2 * kb + 1][0]);
            A[h][kb][3] = htanh2(C[h][2 * kb + 1][1]);
        }
}
__device__ __forceinline__ void repack_id2h(const uint32_t C[2][8][2], uint32_t A[2][4][4]) {
#pragma unroll
    for (int h = 0; h < 2; h++)
#pragma unroll
        for (int kb = 0; kb < 4; kb++) {
            A[h][kb][0] = C[h][2 * kb][0];
            A[h][kb][1] = C[h][2 * kb][1];
            A[h][kb][2] = C[h][2 * kb + 1][0];
            A[h][kb][3] = C[h][2 * kb + 1][1];
        }
}

__global__ void __launch_bounds__(NTHREADS, 1)
pinn_kernel(Params p) {
    extern __shared__ char smem_raw[];
    __half* smW = reinterpret_cast<__half*>(smem_raw);
    __half* smIN = smW + W_HALFS;
    float* smF = reinterpret_cast<float*>(smem_raw + (W_HALFS + 2 * IN_HALFS) * 2);
    uint32_t* smPB = reinterpret_cast<uint32_t*>(
        smem_raw + (W_HALFS + 2 * IN_HALFS) * 2 + F32_FLOATS * 4);
    const int tid = threadIdx.x;

    // ---- fold in the pass-through copy (24576 floats = 6144 float4, 16 blocks x 384) ----
    if (blockIdx.x < 16) {
        int i = blockIdx.x * NTHREADS + tid;
        int j = i & 1023;
        int m = i >> 10;
        const float* srcs[6] = {p.col0, p.col1, p.col2, p.row0, p.row1, p.row2};
        const float4* s4 = reinterpret_cast<const float4*>(srcs[m]) + j;
        reinterpret_cast<float4*>(p.out + p.B)[i] = *s4;
    }

    // ---- stage weights (fp32 -> fp16, padded stride) + input tiles + scalars ----
    {
        const float* gsrc[NMAT] = {p.m2_w, p.m3_w, p.a0_w, p.a1_w, p.a2_w,
                                   p.col0, p.col1, p.col2, p.row0, p.row1, p.row2};
#pragma unroll
        for (int m = 0; m < NMAT; m++) {
            const float* src = gsrc[m];
            __half* dst = smW + m * MAT_HALFS;
            for (int i = tid; i < 4096; i += NTHREADS)
                dst[(i >> 6) * WST + (i & 63)] = __float2half_rn(src[i]);
        }
        // m1 input tile: rows 0..2 = m1_w, row 3 = m1_b, rows 4..15 = 0
        for (int i = tid; i < 1024; i += NTHREADS) {
            int r = i >> 6, n = i & 63;
            float v = (r < 3) ? p.m1_w[r * 64 + n] : (r == 3 ? p.m1_b[n] : 0.f);
            smIN[IN_M1 * IN_HALFS + r * WST + n] = __float2half_rn(v);
        }
        // start input tile: rows 0..1 = start_w, row 2 = start_b, rows 3..15 = 0
        for (int i = tid; i < 1024; i += NTHREADS) {
            int r = i >> 6, n = i & 63;
            float v = (r < 2) ? p.start_w[r * 64 + n] : (r == 2 ? p.start_b[n] : 0.f);
            smIN[IN_ST * IN_HALFS + r * WST + n] = __float2half_rn(v);
        }
        if (tid < 64) smF[F_EW + tid] = p.end_w[tid];
        if (tid < 32) {
            int nt = tid >> 2, tg = tid & 3;
            int j0 = nt * 8 + tg * 2;
            smPB[PB_M2 + tid]      = pack2(p.m2_b[j0], p.m2_b[j0 + 1]);
            smPB[PB_M3 + tid]      = pack2(p.m3_b[j0], p.m3_b[j0 + 1]);
            smPB[PB_A0 + tid]      = pack2(p.a0_b[j0], p.a0_b[j0 + 1]);
            smPB[PB_A0 + 32 + tid] = pack2(p.a1_b[j0], p.a1_b[j0 + 1]);
            smPB[PB_A0 + 64 + tid] = pack2(p.a2_b[j0], p.a2_b[j0 + 1]);
        }
    }
    __syncthreads();

    const int lane = tid & 31, warp = tid >> 5;
    const int g = lane >> 2, tig = lane & 3;
    const float eb = p.end_b[0];

    for (int tile = blockIdx.x; tile < p.ntiles; tile += gridDim.x) {
        const int rowbase = tile * TILE_ROWS + warp * 32;   // 32 rows per warp
        if (rowbase >= p.B) continue;   // tail tile: whole warps drop out (no sync in loop)

        uint32_t Mst[2][4][4];  // hypernet state (f16 A-frags)
        uint32_t A[2][4][4];    // main-net h (f16 A-frags)
        uint32_t Ca[2][8][2];
        uint32_t Cc[2][8][2];

        // ---- input A-fragments: K=16, only k<4 nonzero ----
        uint32_t Am[2][4], Ai[2][4];
#pragma unroll
        for (int h = 0; h < 2; h++) {
            const int rlo = rowbase + h * 16 + g, rhi = rlo + 8;
            // m1: k0=beta, k1=nu, k2=rho, k3=1(bias)
            uint32_t lo, hi;
            if (tig == 0)      { lo = pack2(p.beta[rlo], p.nu[rlo]); hi = pack2(p.beta[rhi], p.nu[rhi]); }
            else if (tig == 1) { lo = pack2(p.rho[rlo], 1.f);        hi = pack2(p.rho[rhi], 1.f); }
            else               { lo = 0u; hi = 0u; }
            Am[h][0] = lo; Am[h][1] = hi; Am[h][2] = 0u; Am[h][3] = 0u;
            // start: k0=x, k1=t, k2=1(bias)
            if (tig == 0)      { lo = pack2(p.x[rlo], p.t[rlo]); hi = pack2(p.x[rhi], p.t[rhi]); }
            else if (tig == 1) { lo = pack2(1.f, 0.f);           hi = pack2(1.f, 0.f); }
            else               { lo = 0u; hi = 0u; }
            Ai[h][0] = lo; Ai[h][1] = hi; Ai[h][2] = 0u; Ai[h][3] = 0u;
        }

        // ---- both input layers as one fused K=16 GEMM pair ----
        gemm_in(Ca, Am, Cc, Ai,
                smIN + IN_M1 * IN_HALFS, smIN + IN_ST * IN_HALFS, lane);
        repack_tanh2h(Ca, Mst);   // hypernet h1
        repack_tanh2h(Cc, A);     // main-net h0

        // m2, m3 (tanh)
        gemm64x2h(Ca, Mst, smW + M_M2 * MAT_HALFS, lane);
        add_bias2h(Ca, smPB + PB_M2, tig);
        repack_tanh2h(Ca, Mst);
        gemm64x2h(Ca, Mst, smW + M_M3 * MAT_HALFS, lane);
        add_bias2h(Ca, smPB + PB_M3, tig);
        repack_tanh2h(Ca, Mst);

        // ---- 3x: alpha_l = relu(M @ a_l); h = tanh(((h @ col_l) * alpha_l) @ row_l) ----
#pragma unroll
        for (int l = 0; l < 3; l++) {
            gemm64x2h(Ca, Mst, smW + (M_A0 + l) * MAT_HALFS, lane);
            add_bias2h(Ca, smPB + PB_A0 + 32 * l, tig);
            gemm64x2h(Cc, A, smW + (M_C0 + l) * MAT_HALFS, lane);
#pragma unroll
            for (int h = 0; h < 2; h++)
#pragma unroll
                for (int nt = 0; nt < 8; nt++) {
                    Cc[h][nt][0] = hmul2u(Cc[h][nt][0], hrelu2(Ca[h][nt][0]));
                    Cc[h][nt][1] = hmul2u(Cc[h][nt][1], hrelu2(Ca[h][nt][1]));
                }
            repack_id2h(Cc, A);
            gemm64x2h(Ca, A, smW + (M_R0 + l) * MAT_HALFS, lane);
            repack_tanh2h(Ca, A);
        }

        // ---- out = h @ end_w + end_b (f32 dot) ----
#pragma unroll
        for (int h = 0; h < 2; h++) {
            const int rlo = rowbase + h * 16 + g, rhi = rlo + 8;
            float slo = 0.f, shi = 0.f;
#pragma unroll
            for (int kb = 0; kb < 4; kb++) {
                int j0 = kb * 16 + tig * 2;
                float2 f;
                f = unpack2(A[h][kb][0]); slo += f.x * smF[F_EW + j0]     + f.y * smF[F_EW + j0 + 1];
                f = unpack2(A[h][kb][1]); shi += f.x * smF[F_EW + j0]     + f.y * smF[F_EW + j0 + 1];
                f = unpack2(A[h][kb][2]); slo += f.x * smF[F_EW + j0 + 8] + f.y * smF[F_EW + j0 + 9];
                f = unpack2(A[h][kb][3]); shi += f.x * smF[F_EW + j0 + 8] + f.y * smF[F_EW + j0 + 9];
            }
            slo += __shfl_xor_sync(0xFFFFFFFFu, slo, 1);
            slo += __shfl_xor_sync(0xFFFFFFFFu, slo, 2);
            shi += __shfl_xor_sync(0xFFFFFFFFu, shi, 1);
            shi += __shfl_xor_sync(0xFFFFFFFFu, shi, 2);
            if (tig == 0) {
                p.out[rlo] = slo + eb;
                p.out[rhi] = shi + eb;
            }
        }
    }
}

extern "C" void kernel_launch(void* const* d_in, const int* in_sizes, int n_in,
                              void* d_out, int out_size) {
    (void)n_in; (void)out_size;
    Params p;
    p.x       = (const float*)d_in[0];
    p.t       = (const float*)d_in[1];
    p.beta    = (const float*)d_in[2];
    p.nu      = (const float*)d_in[3];
    p.rho     = (const float*)d_in[4];
    p.start_w = (const float*)d_in[5];
    p.start_b = (const float*)d_in[6];
    p.end_w   = (const float*)d_in[7];
    p.end_b   = (const float*)d_in[8];
    p.m1_w    = (const float*)d_in[9];
    p.m1_b    = (const float*)d_in[10];
    p.m2_w    = (const float*)d_in[11];
    p.m2_b    = (const float*)d_in[12];
    p.m3_w    = (const float*)d_in[13];
    p.m3_b    = (const float*)d_in[14];
    p.a0_w    = (const float*)d_in[15];
    p.a0_b    = (const float*)d_in[16];
    p.a1_w    = (const float*)d_in[17];
    p.a1_b    = (const float*)d_in[18];
    p.a2_w    = (const float*)d_in[19];
    p.a2_b    = (const float*)d_in[20];
    p.col0    = (const float*)d_in[21];
    p.col1    = (const float*)d_in[22];
    p.col2    = (const float*)d_in[23];
    p.row0    = (const float*)d_in[24];
    p.row1    = (const float*)d_in[25];
    p.row2    = (const float*)d_in[26];
    p.out     = (float*)d_out;

    p.B = in_sizes[0];
    p.ntiles = (p.B + TILE_ROWS - 1) / TILE_ROWS;

    int dev = 0, nsm = 148;
    cudaGetDevice(&dev);
    cudaDeviceGetAttribute(&nsm, cudaDevAttrMultiProcessorCount, dev);
    int grid = nsm < 16 ? 16 : nsm;   // >=16 so the folded copy covers all 6 matrices
    if (grid > p.ntiles) grid = p.ntiles;

    cudaFuncSetAttribute(pinn_kernel, cudaFuncAttributeMaxDynamicSharedMemorySize, SMEM_BYTES);
    pinn_kernel<<<grid, NTHREADS, SMEM_BYTES>>>(p);
}

// round 13
// speedup vs baseline: 1.0468x; 1.0058x over previous
#include <cuda_runtime.h>
#include <cuda_fp16.h>
#include <stdint.h>

#define NTHREADS 384
#define TILE_ROWS 384                // 12 warps x 32 rows
#define WST 72                       // padded smem stride (halfs) -> conflict-free ldmatrix
#define MAT_HALFS (64 * WST)         // 4608 halfs per 64x64 matrix
#define NMAT 11
#define W_HALFS (NMAT * MAT_HALFS)
#define IN_HALFS (16 * WST)          // 16x64 input-layer tile (K=16)
#define PB_WORDS 160
#define SMEM_BYTES ((W_HALFS + MAT_HALFS + 2 * IN_HALFS) * 2 + PB_WORDS * 4)

// packed f16x2 bias region offsets (uint32 words)
#define PB_M2 0
#define PB_M3 32
#define PB_A0 64     // +32 per alpha head

// matrix slots in smem
#define M_M2 0
#define M_M3 1
#define M_A0 2
#define M_A1 3
#define M_A2 4
#define M_C0 5
#define M_R0 8
#define M_EW 11      // 64x16 used: col0 = end_w
// input-layer tiles sit after the 12 square matrices
#define IN_M1 0
#define IN_ST 1

struct Params {
    const float *x, *t, *beta, *nu, *rho;
    const float *start_w, *start_b, *end_w, *end_b;
    const float *m1_w, *m1_b, *m2_w, *m2_b, *m3_w, *m3_b;
    const float *a0_w, *a0_b, *a1_w, *a1_b, *a2_w, *a2_b;
    const float *col0, *col1, *col2, *row0, *row1, *row2;
    float* out;
    int ntiles;
    int B;
};

__device__ __forceinline__ uint32_t pack2(float lo, float hi) {
    __half2 h = __floats2half2_rn(lo, hi);
    return *reinterpret_cast<uint32_t*>(&h);
}
__device__ __forceinline__ uint32_t htanh2(uint32_t v) {
    uint32_t y;
    asm("tanh.approx.f16x2 %0, %1;" : "=r"(y) : "r"(v));
    return y;
}
__device__ __forceinline__ uint32_t hadd2u(uint32_t a, uint32_t b) {
    __half2 r = __hadd2(*reinterpret_cast<__half2*>(&a), *reinterpret_cast<__half2*>(&b));
    return *reinterpret_cast<uint32_t*>(&r);
}
__device__ __forceinline__ uint32_t hmul2u(uint32_t a, uint32_t b) {
    __half2 r = __hmul2(*reinterpret_cast<__half2*>(&a), *reinterpret_cast<__half2*>(&b));
    return *reinterpret_cast<uint32_t*>(&r);
}
__device__ __forceinline__ uint32_t hrelu2(uint32_t a) {
    __half2 z = __float2half2_rn(0.f);
    __half2 r = __hmax2(*reinterpret_cast<__half2*>(&a), z);
    return *reinterpret_cast<uint32_t*>(&r);
}
__device__ __forceinline__ void prefetchL2(const void* p) {
    asm volatile("prefetch.global.L2 [%0];" :: "l"(p));
}

// f16-accumulator MMA
__device__ __forceinline__ void mma16816h(uint32_t* c, const uint32_t* a, uint32_t b0, uint32_t b1) {
    asm volatile(
        "mma.sync.aligned.m16n8k16.row.col.f16.f16.f16.f16 "
        "{%0,%1}, {%2,%3,%4,%5}, {%6,%7}, {%0,%1};\n"
        : "+r"(c[0]), "+r"(c[1])
        : "r"(a[0]), "r"(a[1]), "r"(a[2]), "r"(a[3]), "r"(b0), "r"(b1));
}
// f32-accumulator MMA (final output layer)
__device__ __forceinline__ void mma16816f(float* c, const uint32_t* a, uint32_t b0, uint32_t b1) {
    asm volatile(
        "mma.sync.aligned.m16n8k16.row.col.f32.f16.f16.f32 "
        "{%0,%1,%2,%3}, {%4,%5,%6,%7}, {%8,%9}, {%0,%1,%2,%3};\n"
        : "+f"(c[0]), "+f"(c[1]), "+f"(c[2]), "+f"(c[3])
        : "r"(a[0]), "r"(a[1]), "r"(a[2]), "r"(a[3]), "r"(b0), "r"(b1));
}

__device__ __forceinline__ void ldsm4t(uint32_t& r0, uint32_t& r1, uint32_t& r2, uint32_t& r3,
                                       uint32_t addr) {
    asm volatile("ldmatrix.sync.aligned.m8n8.x4.trans.shared.b16 {%0,%1,%2,%3}, [%4];\n"
                 : "=r"(r0), "=r"(r1), "=r"(r2), "=r"(r3)
                 : "r"(addr));
}

// Dual-tile f16-accum GEMM: C[h][8][2] = A[h](16x64) @ W(64x64), h=0,1.
__device__ __forceinline__ void gemm64x2h(uint32_t C[2][8][2], const uint32_t A[2][4][4],
                                          const __half* W, int lane) {
#pragma unroll
    for (int h = 0; h < 2; h++)
#pragma unroll
        for (int nt = 0; nt < 8; nt++) { C[h][nt][0] = 0u; C[h][nt][1] = 0u; }

    uint32_t base = (uint32_t)__cvta_generic_to_shared(
        W + (lane & 15) * WST + ((lane & 16) ? 8 : 0));
#pragma unroll
    for (int nt2 = 0; nt2 < 4; nt2++) {
#pragma unroll
        for (int kb = 0; kb < 4; kb++) {
            uint32_t b0, b1, b2, b3;
            ldsm4t(b0, b1, b2, b3, base + (uint32_t)((kb * 16 * WST + nt2 * 16) * 2));
            mma16816h(C[0][nt2 * 2],     A[0][kb], b0, b1);
            mma16816h(C[0][nt2 * 2 + 1], A[0][kb], b2, b3);
            mma16816h(C[1][nt2 * 2],     A[1][kb], b0, b1);
            mma16816h(C[1][nt2 * 2 + 1], A[1][kb], b2, b3);
        }
    }
}

// Fused input layers: K=16 GEMMs for m1 ([beta,nu,rho,1]) and start ([x,t,1]).
__device__ __forceinline__ void gemm_in(uint32_t Cm[2][8][2], const uint32_t Am[2][4],
                                        uint32_t Ci[2][8][2], const uint32_t Ai[2][4],
                                        const __half* Wm, const __half* Wi, int lane) {
#pragma unroll
    for (int h = 0; h < 2; h++)
#pragma unroll
        for (int nt = 0; nt < 8; nt++) {
            Cm[h][nt][0] = 0u; Cm[h][nt][1] = 0u;
            Ci[h][nt][0] = 0u; Ci[h][nt][1] = 0u;
        }
    uint32_t off = (lane & 15) * WST + ((lane & 16) ? 8 : 0);
    uint32_t basem = (uint32_t)__cvta_generic_to_shared(Wm + off);
    uint32_t basei = (uint32_t)__cvta_generic_to_shared(Wi + off);
#pragma unroll
    for (int nt2 = 0; nt2 < 4; nt2++) {
        uint32_t d = (uint32_t)((nt2 * 16) * 2);
        uint32_t m0, m1, m2, m3, i0, i1, i2, i3;
        ldsm4t(m0, m1, m2, m3, basem + d);
        ldsm4t(i0, i1, i2, i3, basei + d);
        mma16816h(Cm[0][nt2 * 2],     Am[0], m0, m1);
        mma16816h(Cm[0][nt2 * 2 + 1], Am[0], m2, m3);
        mma16816h(Cm[1][nt2 * 2],     Am[1], m0, m1);
        mma16816h(Cm[1][nt2 * 2 + 1], Am[1], m2, m3);
        mma16816h(Ci[0][nt2 * 2],     Ai[0], i0, i1);
        mma16816h(Ci[0][nt2 * 2 + 1], Ai[0], i2, i3);
        mma16816h(Ci[1][nt2 * 2],     Ai[1], i0, i1);
        mma16816h(Ci[1][nt2 * 2 + 1], Ai[1], i2, i3);
    }
}

// Output layer: Co[h][4] (f32) = A[h](16x64) @ EW(64x8, col0 = end_w)
__device__ __forceinline__ void gemm_out(float Co[2][4], const uint32_t A[2][4][4],
                                         const __half* W, int lane) {
#pragma unroll
    for (int h = 0; h < 2; h++)
#pragma unroll
        for (int q = 0; q < 4; q++) Co[h][q] = 0.f;
    uint32_t base = (uint32_t)__cvta_generic_to_shared(
        W + (lane & 15) * WST + ((lane & 16) ? 8 : 0));
#pragma unroll
    for (int kb = 0; kb < 4; kb++) {
        uint32_t b0, b1, b2, b3;
        ldsm4t(b0, b1, b2, b3, base + (uint32_t)((kb * 16 * WST) * 2));
        mma16816f(Co[0], A[0][kb], b0, b1);
        mma16816f(Co[1], A[1][kb], b0, b1);
    }
}

__device__ __forceinline__ void add_bias2h(uint32_t C[2][8][2], const uint32_t* pb, int tig) {
#pragma unroll
    for (int h = 0; h < 2; h++)
#pragma unroll
        for (int nt = 0; nt < 8; nt++) {
            uint32_t b = pb[nt * 4 + tig];
            C[h][nt][0] = hadd2u(C[h][nt][0], b);
            C[h][nt][1] = hadd2u(C[h][nt][1], b);
        }
}

// f16 C layout == A-fragment layout: repack is a register rename (+ tanh)
__device__ __forceinline__ void repack_tanh2h(const uint32_t C[2][8][2], uint32_t A[2][4][4]) {
#pragma unroll
    for (int h = 0; h < 2; h++)
#pragma unroll
        for (int kb = 0; kb < 4; kb++) {
            A[h][kb][0] = htanh2(C[h][2 * kb][0]);
            A[h][kb][1] = htanh2(C[h][2 * kb][1]);
            A[h][kb][2] = htanh2(C[h][2 * kb + 1][0]);
            A[h][kb][3] = htanh2(C[h][2 * kb + 1][1]);
        }
}
__device__ __forceinline__ void repack_id2h(const uint32_t C[2][8][2], uint32_t A[2][4][4]) {
#pragma unroll
    for (int h = 0; h < 2; h++)
#pragma unroll
        for (int kb = 0; kb < 4; kb++) {
            A[h][kb][0] = C[h][2 * kb][0];
            A[h][kb][1] = C[h][2 * kb][1];
            A[h][kb][2] = C[h][2 * kb + 1][0];
            A[h][kb][3] = C[h][2 * kb + 1][1];
        }
}

__global__ void __launch_bounds__(NTHREADS, 1)
pinn_kernel(Params p) {
    extern __shared__ char smem_raw[];
    __half* smW = reinterpret_cast<__half*>(smem_raw);
    __half* smIN = smW + W_HALFS + MAT_HALFS;
    uint32_t* smPB = reinterpret_cast<uint32_t*>(
        smem_raw + (W_HALFS + MAT_HALFS + 2 * IN_HALFS) * 2);
    const int tid = threadIdx.x;

    // ---- fold in the pass-through copy (24576 floats = 6144 float4, 16 blocks x 384) ----
    if (blockIdx.x < 16) {
        int i = blockIdx.x * NTHREADS + tid;
        int j = i & 1023;
        int m = i >> 10;
        const float* srcs[6] = {p.col0, p.col1, p.col2, p.row0, p.row1, p.row2};
        const float4* s4 = reinterpret_cast<const float4*>(srcs[m]) + j;
        reinterpret_cast<float4*>(p.out + p.B)[i] = *s4;
    }

    // ---- stage weights (fp32 -> fp16, padded stride) + input/output tiles ----
    {
        const float* gsrc[NMAT] = {p.m2_w, p.m3_w, p.a0_w, p.a1_w, p.a2_w,
                                   p.col0, p.col1, p.col2, p.row0, p.row1, p.row2};
#pragma unroll
        for (int m = 0; m < NMAT; m++) {
            const float* src = gsrc[m];
            __half* dst = smW + m * MAT_HALFS;
            for (int i = tid; i < 4096; i += NTHREADS)
                dst[(i >> 6) * WST + (i & 63)] = __float2half_rn(src[i]);
        }
        // end_w tile: 64 rows x 16 cols, col0 = end_w, rest 0
        for (int i = tid; i < 1024; i += NTHREADS) {
            int r = i >> 4, c = i & 15;
            float v = (c == 0) ? p.end_w[r] : 0.f;
            smW[M_EW * MAT_HALFS + r * WST + c] = __float2half_rn(v);
        }
        // m1 input tile: rows 0..2 = m1_w, row 3 = m1_b, rows 4..15 = 0
        for (int i = tid; i < 1024; i += NTHREADS) {
            int r = i >> 6, n = i & 63;
            float v = (r < 3) ? p.m1_w[r * 64 + n] : (r == 3 ? p.m1_b[n] : 0.f);
            smIN[IN_M1 * IN_HALFS + r * WST + n] = __float2half_rn(v);
        }
        // start input tile: rows 0..1 = start_w, row 2 = start_b, rows 3..15 = 0
        for (int i = tid; i < 1024; i += NTHREADS) {
            int r = i >> 6, n = i & 63;
            float v = (r < 2) ? p.start_w[r * 64 + n] : (r == 2 ? p.start_b[n] : 0.f);
            smIN[IN_ST * IN_HALFS + r * WST + n] = __float2half_rn(v);
        }
        if (tid < 32) {
            int nt = tid >> 2, tg = tid & 3;
            int j0 = nt * 8 + tg * 2;
            smPB[PB_M2 + tid]      = pack2(p.m2_b[j0], p.m2_b[j0 + 1]);
            smPB[PB_M3 + tid]      = pack2(p.m3_b[j0], p.m3_b[j0 + 1]);
            smPB[PB_A0 + tid]      = pack2(p.a0_b[j0], p.a0_b[j0 + 1]);
            smPB[PB_A0 + 32 + tid] = pack2(p.a1_b[j0], p.a1_b[j0 + 1]);
            smPB[PB_A0 + 64 + tid] = pack2(p.a2_b[j0], p.a2_b[j0 + 1]);
        }
    }
    __syncthreads();

    const int lane = tid & 31, warp = tid >> 5;
    const int g = lane >> 2, tig = lane & 3;
    const float eb = p.end_b[0];

    for (int tile = blockIdx.x; tile < p.ntiles; tile += gridDim.x) {
        const int rowbase = tile * TILE_ROWS + warp * 32;   // 32 rows per warp
        if (rowbase >= p.B) continue;   // tail tile: whole warps drop out (no sync in loop)

        // L2-prefetch next grid-stride tile's inputs (128B-aligned lines, no reg cost)
        {
            int nb = (tile + gridDim.x) * TILE_ROWS + warp * 32;
            if (nb < p.B && lane == 0) {
                prefetchL2(p.x + nb);
                prefetchL2(p.t + nb);
                prefetchL2(p.beta + nb);
                prefetchL2(p.nu + nb);
                prefetchL2(p.rho + nb);
            }
        }

        uint32_t Mst[2][4][4];  // hypernet state (f16 A-frags)
        uint32_t A[2][4][4];    // main-net h (f16 A-frags)
        uint32_t Ca[2][8][2];
        uint32_t Cc[2][8][2];

        // ---- input A-fragments: K=16, only k<4 nonzero ----
        uint32_t Am[2][4], Ai[2][4];
#pragma unroll
        for (int h = 0; h < 2; h++) {
            const int rlo = rowbase + h * 16 + g, rhi = rlo + 8;
            uint32_t lo, hi;
            if (tig == 0)      { lo = pack2(p.beta[rlo], p.nu[rlo]); hi = pack2(p.beta[rhi], p.nu[rhi]); }
            else if (tig == 1) { lo = pack2(p.rho[rlo], 1.f);        hi = pack2(p.rho[rhi], 1.f); }
            else               { lo = 0u; hi = 0u; }
            Am[h][0] = lo; Am[h][1] = hi; Am[h][2] = 0u; Am[h][3] = 0u;
            if (tig == 0)      { lo = pack2(p.x[rlo], p.t[rlo]); hi = pack2(p.x[rhi], p.t[rhi]); }
            else if (tig == 1) { lo = pack2(1.f, 0.f);           hi = pack2(1.f, 0.f); }
            else               { lo = 0u; hi = 0u; }
            Ai[h][0] = lo; Ai[h][1] = hi; Ai[h][2] = 0u; Ai[h][3] = 0u;
        }

        // ---- both input layers as one fused K=16 GEMM pair ----
        gemm_in(Ca, Am, Cc, Ai,
                smIN + IN_M1 * IN_HALFS, smIN + IN_ST * IN_HALFS, lane);
        repack_tanh2h(Ca, Mst);   // hypernet h1
        repack_tanh2h(Cc, A);     // main-net h0

        // m2, m3 (tanh)
        gemm64x2h(Ca, Mst, smW + M_M2 * MAT_HALFS, lane);
        add_bias2h(Ca, smPB + PB_M2, tig);
        repack_tanh2h(Ca, Mst);
        gemm64x2h(Ca, Mst, smW + M_M3 * MAT_HALFS, lane);
        add_bias2h(Ca, smPB + PB_M3, tig);
        repack_tanh2h(Ca, Mst);

        // ---- 3x: alpha_l = relu(M @ a_l); h = tanh(((h @ col_l) * alpha_l) @ row_l) ----
#pragma unroll
        for (int l = 0; l < 3; l++) {
            gemm64x2h(Ca, Mst, smW + (M_A0 + l) * MAT_HALFS, lane);
            add_bias2h(Ca, smPB + PB_A0 + 32 * l, tig);
            gemm64x2h(Cc, A, smW + (M_C0 + l) * MAT_HALFS, lane);
#pragma unroll
            for (int h = 0; h < 2; h++)
#pragma unroll
                for (int nt = 0; nt < 8; nt++) {
                    Cc[h][nt][0] = hmul2u(Cc[h][nt][0], hrelu2(Ca[h][nt][0]));
                    Cc[h][nt][1] = hmul2u(Cc[h][nt][1], hrelu2(Ca[h][nt][1]));
                }
            repack_id2h(Cc, A);
            gemm64x2h(Ca, A, smW + (M_R0 + l) * MAT_HALFS, lane);
            repack_tanh2h(Ca, A);
        }

        // ---- out = h @ end_w + end_b via f32-accum MMA (no shfl) ----
        {
            float Co[2][4];
            gemm_out(Co, A, smW + M_EW * MAT_HALFS, lane);
            if (tig == 0) {
#pragma unroll
                for (int h = 0; h < 2; h++) {
                    const int rlo = rowbase + h * 16 + g;
                    p.out[rlo]     = Co[h][0] + eb;
                    p.out[rlo + 8] = Co[h][2] + eb;
                }
            }
        }
    }
}

extern "C" void kernel_launch(void* const* d_in, const int* in_sizes, int n_in,
                              void* d_out, int out_size) {
    (void)n_in; (void)out_size;
    Params p;
    p.x       = (const float*)d_in[0];
    p.t       = (const float*)d_in[1];
    p.beta    = (const float*)d_in[2];
    p.nu      = (const float*)d_in[3];
    p.rho     = (const float*)d_in[4];
    p.start_w = (const float*)d_in[5];
    p.start_b = (const float*)d_in[6];
    p.end_w   = (const float*)d_in[7];
    p.end_b   = (const float*)d_in[8];
    p.m1_w    = (const float*)d_in[9];
    p.m1_b    = (const float*)d_in[10];
    p.m2_w    = (const float*)d_in[11];
    p.m2_b    = (const float*)d_in[12];
    p.m3_w    = (const float*)d_in[13];
    p.m3_b    = (const float*)d_in[14];
    p.a0_w    = (const float*)d_in[15];
    p.a0_b    = (const float*)d_in[16];
    p.a1_w    = (const float*)d_in[17];
    p.a1_b    = (const float*)d_in[18];
    p.a2_w    = (const float*)d_in[19];
    p.a2_b    = (const float*)d_in[20];
    p.col0    = (const float*)d_in[21];
    p.col1    = (const float*)d_in[22];
    p.col2    = (const float*)d_in[23];
    p.row0    = (const float*)d_in[24];
    p.row1    = (const float*)d_in[25];
    p.row2    = (const float*)d_in[26];
    p.out     = (float*)d_out;

    p.B = in_sizes[0];
    p.ntiles = (p.B + TILE_ROWS - 1) / TILE_ROWS;

    int dev = 0, nsm = 148;
    cudaGetDevice(&dev);
    cudaDeviceGetAttribute(&nsm, cudaDevAttrMultiProcessorCount, dev);
    int grid = nsm < 16 ? 16 : nsm;   // >=16 so the folded copy covers all 6 matrices
    if (grid > p.ntiles) grid = p.ntiles;

    cudaFuncSetAttribute(pinn_kernel, cudaFuncAttributeMaxDynamicSharedMemorySize, SMEM_BYTES);
    pinn_kernel<<<grid, NTHREADS, SMEM_BYTES>>>(p);
}